// round 8
// baseline (speedup 1.0000x reference)
#include <cuda_runtime.h>
#include <cuda_bf16.h>
#include <stdint.h>
#include <math.h>

#define NN 8192
#define DD 512
#define SCALE 0.044194173824159216f

// ----------------- device scratch (allocation-free rule) -----------------
__device__ float g_v[NN * DD];
__device__ __nv_bfloat16 gx_hi[NN * DD], gx_lo[NN * DD];
__device__ __nv_bfloat16 gw_hi[3 * DD * DD], gw_lo[3 * DD * DD];
__device__ __nv_bfloat16 gq_hi[NN * DD], gq_lo[NN * DD];
__device__ __nv_bfloat16 gk_hi[NN * DD], gk_lo[NN * DD];
__device__ __nv_bfloat16 gvt_hi[DD * NN], gvt_lo[DD * NN];
__device__ __nv_bfloat16 gP_hi[(size_t)NN * NN], gP_lo[(size_t)NN * NN];
__device__ float g_lpart[64 * NN];
__device__ float g_l[NN];

// ----------------- helpers -----------------
__device__ __forceinline__ uint32_t smem_u32(const void* p) {
    uint32_t a;
    asm("{ .reg .u64 t; cvta.to.shared.u64 t, %1; cvt.u32.u64 %0, t; }" : "=r"(a) : "l"(p));
    return a;
}
__device__ __forceinline__ uint32_t pack2(__nv_bfloat16 a, __nv_bfloat16 b) {
    return (uint32_t)__bfloat16_as_ushort(a) | ((uint32_t)__bfloat16_as_ushort(b) << 16);
}
__device__ __forceinline__ void cpa16(uint32_t dst, const void* src) {
    asm volatile("cp.async.cg.shared.global [%0], [%1], 16;" :: "r"(dst), "l"(src));
}
__device__ __forceinline__ void cpa_commit() {
    asm volatile("cp.async.commit_group;" ::: "memory");
}
__device__ __forceinline__ void ldsm4(uint32_t* r, uint32_t addr) {
    asm volatile("ldmatrix.sync.aligned.m8n8.x4.shared.b16 {%0,%1,%2,%3}, [%4];"
                 : "=r"(r[0]), "=r"(r[1]), "=r"(r[2]), "=r"(r[3]) : "r"(addr));
}
__device__ __forceinline__ void mma16816(float* c, const uint32_t* a, const uint32_t* b) {
    asm volatile(
        "mma.sync.aligned.m16n8k16.row.col.f32.bf16.bf16.f32 "
        "{%0,%1,%2,%3}, {%4,%5,%6,%7}, {%8,%9}, {%0,%1,%2,%3};"
        : "+f"(c[0]), "+f"(c[1]), "+f"(c[2]), "+f"(c[3])
        : "r"(a[0]), "r"(a[1]), "r"(a[2]), "r"(a[3]), "r"(b[0]), "r"(b[1]));
}

// ---------------------------------------------------------------------------
// Split x and Wq/Wk/Wv into bf16 hi/lo
// ---------------------------------------------------------------------------
__global__ __launch_bounds__(256)
void split_kernel(const float* __restrict__ x, const float* __restrict__ Wq,
                  const float* __restrict__ Wk, const float* __restrict__ Wv) {
    int i4 = blockIdx.x * 256 + threadIdx.x;
    const float4* src;
    uint2 *oh, *ol;
    int off;
    if (i4 < NN * DD / 4) {
        src = (const float4*)x; oh = (uint2*)gx_hi; ol = (uint2*)gx_lo; off = i4;
    } else {
        int r = i4 - NN * DD / 4;
        int wi = r >> 16, rr = r & 65535;
        const float* w = (wi == 0) ? Wq : (wi == 1) ? Wk : Wv;
        src = (const float4*)w; off = rr;
        oh = (uint2*)(gw_hi + (size_t)wi * DD * DD);
        ol = (uint2*)(gw_lo + (size_t)wi * DD * DD);
    }
    float4 v = src[off];
    __nv_bfloat16 h0 = __float2bfloat16(v.x), h1 = __float2bfloat16(v.y);
    __nv_bfloat16 h2 = __float2bfloat16(v.z), h3 = __float2bfloat16(v.w);
    uint2 H, L;
    H.x = pack2(h0, h1);
    H.y = pack2(h2, h3);
    L.x = pack2(__float2bfloat16(v.x - __bfloat162float(h0)),
                __float2bfloat16(v.y - __bfloat162float(h1)));
    L.y = pack2(__float2bfloat16(v.z - __bfloat162float(h2)),
                __float2bfloat16(v.w - __bfloat162float(h3)));
    oh[off] = H;
    ol[off] = L;
}

// ---------------------------------------------------------------------------
// Fused-term GEMM body: CTA 256x128, 512 threads, warps 4x4 (warp 64x32).
// Stage buffer (61440B): Ah@0 (256x80), Al@20480, Bh@40960 (128x80), Bl@51200.
// 3-stage ring, wait_group 1, one barrier per chunk.
// ---------------------------------------------------------------------------
#define STAGE_BYTES 61440

#define FUSED_STAGE(AH, AL, BH, BL, cc, buf, LDA)                                 \
    {                                                                             \
        int kk_ = (cc) * 32;                                                      \
        uint32_t d_ = sb + (buf) * STAGE_BYTES;                                   \
        const __nv_bfloat16* ah_ = (AH) + (size_t)m0 * (LDA) + kk_;               \
        const __nv_bfloat16* al_ = (AL) + (size_t)m0 * (LDA) + kk_;               \
        const __nv_bfloat16* bh_ = (BH) + (size_t)n0 * (LDA) + kk_;               \
        const __nv_bfloat16* bl_ = (BL) + (size_t)n0 * (LDA) + kk_;               \
        _Pragma("unroll")                                                         \
        for (int i_ = 0; i_ < 2; ++i_) {                                          \
            int r_ = sr + i_ * 128;                                               \
            uint32_t ro_ = r_ * 80 + sc * 16;                                     \
            size_t go_ = (size_t)r_ * (LDA) + sc * 8;                             \
            cpa16(d_ + ro_, ah_ + go_);                                           \
            cpa16(d_ + 20480 + ro_, al_ + go_);                                   \
        }                                                                         \
        {                                                                         \
            uint32_t ro_ = sr * 80 + sc * 16;                                     \
            size_t go_ = (size_t)sr * (LDA) + sc * 8;                             \
            cpa16(d_ + 40960 + ro_, bh_ + go_);                                   \
            cpa16(d_ + 51200 + ro_, bl_ + go_);                                   \
        }                                                                         \
        cpa_commit();                                                             \
    }

#define FUSED_COMPUTE(buf)                                                        \
    {                                                                             \
        uint32_t sA = sb + (buf) * STAGE_BYTES, sB = sA + 40960;                  \
        _Pragma("unroll")                                                         \
        for (int kq = 0; kq < 2; ++kq) {                                          \
            uint32_t ah[4][4], al[4][4];                                          \
            _Pragma("unroll")                                                     \
            for (int mi = 0; mi < 4; ++mi)                                        \
                ldsm4(ah[mi], sA + aOff + mi * 1280 + kq * 32);                   \
            _Pragma("unroll")                                                     \
            for (int mi = 0; mi < 4; ++mi)                                        \
                ldsm4(al[mi], sA + 20480 + aOff + mi * 1280 + kq * 32);           \
            _Pragma("unroll")                                                     \
            for (int nj = 0; nj < 2; ++nj) {                                      \
                uint32_t bh[4], bl[4];                                            \
                ldsm4(bh, sB + bOff + nj * 1280 + kq * 32);                       \
                ldsm4(bl, sB + 10240 + bOff + nj * 1280 + kq * 32);               \
                _Pragma("unroll")                                                 \
                for (int mi = 0; mi < 4; ++mi) {                                  \
                    mma16816(acc[mi][nj * 2], ah[mi], bh);                        \
                    mma16816(acc[mi][nj * 2 + 1], ah[mi], bh + 2);                \
                    mma16816(acc[mi][nj * 2], ah[mi], bl);                        \
                    mma16816(acc[mi][nj * 2 + 1], ah[mi], bl + 2);                \
                    mma16816(acc[mi][nj * 2], al[mi], bh);                        \
                    mma16816(acc[mi][nj * 2 + 1], al[mi], bh + 2);                \
                }                                                                 \
            }                                                                     \
        }                                                                         \
    }

#define FUSED_PRO()                                                               \
    float acc[4][4][4];                                                           \
    _Pragma("unroll")                                                             \
    for (int mi = 0; mi < 4; ++mi)                                                \
        _Pragma("unroll")                                                         \
        for (int ni = 0; ni < 4; ++ni)                                            \
            _Pragma("unroll")                                                     \
            for (int q = 0; q < 4; ++q) acc[mi][ni][q] = 0.0f;                    \
    const int sr = t >> 2, sc = t & 3;                                            \
    const uint32_t aOff = (uint32_t)(wr * 64 + (lane & 15)) * 80 + (lane >> 4) * 16; \
    const uint32_t bOff = (uint32_t)(wc * 32 + (lane & 7) + ((lane >> 4) & 1) * 8) * 80 + \
                          ((lane >> 3) & 1) * 16;

#define FUSED_LOOP(AH, AL, BH, BL, NC, LDA)                                       \
    FUSED_STAGE(AH, AL, BH, BL, 0, 0, LDA);                                       \
    FUSED_STAGE(AH, AL, BH, BL, 1, 1, LDA);                                       \
    for (int cc = 0; cc < (NC); ++cc) {                                           \
        asm volatile("cp.async.wait_group 1;" ::: "memory");                      \
        __syncthreads();                                                          \
        int nx = cc + 2;                                                          \
        if (nx < (NC)) {                                                          \
            int nb = nx % 3;                                                      \
            FUSED_STAGE(AH, AL, BH, BL, nx, nb, LDA);                             \
        }                                                                         \
        FUSED_COMPUTE(cc % 3);                                                    \
    }

// ---------------------------------------------------------------------------
// Tensor-core QKV projection, fused 3-term. z=0:Q, z=1:K (bf16 hi/lo), z=2:V fp32.
// ---------------------------------------------------------------------------
__global__ __launch_bounds__(512, 1)
void proj_kernel(const float* __restrict__ bq, const float* __restrict__ bk,
                 const float* __restrict__ bv) {
    extern __shared__ __align__(128) char smem[];
    const int t = threadIdx.x, wid = t >> 5, lane = t & 31;
    const int z = blockIdx.z;
    const int m0 = blockIdx.y * 256, n0 = blockIdx.x * 128;
    const uint32_t sb = smem_u32(smem);
    const int wr = wid >> 2, wc = wid & 3;
    const __nv_bfloat16* WHz = gw_hi + (size_t)z * DD * DD;
    const __nv_bfloat16* WLz = gw_lo + (size_t)z * DD * DD;

    FUSED_PRO();
    FUSED_LOOP(gx_hi, gx_lo, WHz, WLz, 16, DD);

    const float* bias = (z == 0) ? bq : (z == 1) ? bk : bv;
#pragma unroll
    for (int mi = 0; mi < 4; ++mi) {
#pragma unroll
        for (int h = 0; h < 2; ++h) {
            int row = m0 + wr * 64 + mi * 16 + (lane >> 2) + h * 8;
#pragma unroll
            for (int ni = 0; ni < 4; ++ni) {
                int col = n0 + wc * 32 + ni * 8 + (lane & 3) * 2;
                float2 bb = *(const float2*)(bias + col);
                float v0 = acc[mi][ni][h * 2] + bb.x;
                float v1 = acc[mi][ni][h * 2 + 1] + bb.y;
                if (z == 2) {
                    *(float2*)(g_v + (size_t)row * DD + col) = make_float2(v0, v1);
                } else {
                    __nv_bfloat16* oh = z ? gk_hi : gq_hi;
                    __nv_bfloat16* ol = z ? gk_lo : gq_lo;
                    __nv_bfloat16 h0 = __float2bfloat16(v0), h1 = __float2bfloat16(v1);
                    *(uint32_t*)(oh + (size_t)row * DD + col) = pack2(h0, h1);
                    *(uint32_t*)(ol + (size_t)row * DD + col) =
                        pack2(__float2bfloat16(v0 - __bfloat162float(h0)),
                              __float2bfloat16(v1 - __bfloat162float(h1)));
                }
            }
        }
    }
}

// ---------------------------------------------------------------------------
// V transpose + bf16 split
// ---------------------------------------------------------------------------
__global__ __launch_bounds__(256, 4)
void vtrans_kernel() {
    __shared__ float ts[32][33];
    int j0 = blockIdx.x * 32, d0 = blockIdx.y * 32;
    int tx = threadIdx.x & 31, ty = threadIdx.x >> 5;
#pragma unroll
    for (int i = 0; i < 4; ++i)
        ts[ty + 8 * i][tx] = g_v[(size_t)(j0 + ty + 8 * i) * DD + d0 + tx];
    __syncthreads();
#pragma unroll
    for (int i = 0; i < 4; ++i) {
        float v = ts[tx][ty + 8 * i];
        __nv_bfloat16 h = __float2bfloat16(v);
        __nv_bfloat16 l = __float2bfloat16(v - __bfloat162float(h));
        size_t o = (size_t)(d0 + ty + 8 * i) * NN + j0 + tx;
        gvt_hi[o] = h;
        gvt_lo[o] = l;
    }
}

// ---------------------------------------------------------------------------
// Pass 1: P = exp(scale*Q@K^T + sp + ed), fused 3-term, CTA 256x128.
// ---------------------------------------------------------------------------
__global__ __launch_bounds__(512, 1)
void pass1_kernel(const float* __restrict__ sp, const float* __restrict__ ed) {
    extern __shared__ __align__(128) char smem[];
    float* smem_l = (float*)(smem + 3 * STAGE_BYTES);
    const int t = threadIdx.x, wid = t >> 5, lane = t & 31;
    const int m0 = blockIdx.y * 256, n0 = blockIdx.x * 128;
    const uint32_t sb = smem_u32(smem);
    const int wr = wid >> 2, wc = wid & 3;

    FUSED_PRO();
    FUSED_LOOP(gq_hi, gq_lo, gk_hi, gk_lo, 16, DD);

    // epilogue: bias add, exp, split-store P, row sums
#pragma unroll
    for (int mi = 0; mi < 4; ++mi) {
#pragma unroll
        for (int h = 0; h < 2; ++h) {
            int rloc = wr * 64 + mi * 16 + (lane >> 2) + h * 8;
            size_t rb = (size_t)(m0 + rloc) * NN;
            float rs = 0.0f;
#pragma unroll
            for (int ni = 0; ni < 4; ++ni) {
                int col = n0 + wc * 32 + ni * 8 + (lane & 3) * 2;
                float2 s2 = *(const float2*)(sp + rb + col);
                float2 e2 = *(const float2*)(ed + rb + col);
                float p0 = __expf(acc[mi][ni][h * 2] * SCALE + s2.x + e2.x);
                float p1 = __expf(acc[mi][ni][h * 2 + 1] * SCALE + s2.y + e2.y);
                __nv_bfloat16 h0 = __float2bfloat16(p0), h1 = __float2bfloat16(p1);
                *(uint32_t*)(gP_hi + rb + col) = pack2(h0, h1);
                *(uint32_t*)(gP_lo + rb + col) =
                    pack2(__float2bfloat16(p0 - __bfloat162float(h0)),
                          __float2bfloat16(p1 - __bfloat162float(h1)));
                rs += p0 + p1;
            }
            rs += __shfl_xor_sync(0xffffffffu, rs, 1);
            rs += __shfl_xor_sync(0xffffffffu, rs, 2);
            if ((lane & 3) == 0) smem_l[rloc * 4 + wc] = rs;
        }
    }
    __syncthreads();
    if (t < 256) {
        float s = smem_l[t * 4] + smem_l[t * 4 + 1] + smem_l[t * 4 + 2] + smem_l[t * 4 + 3];
        g_lpart[(size_t)blockIdx.x * NN + m0 + t] = s;
    }
}

// ---------------------------------------------------------------------------
// l reduce (deterministic)
// ---------------------------------------------------------------------------
__global__ void lreduce_kernel() {
    int r = blockIdx.x * 256 + threadIdx.x;
    float s = 0.0f;
    for (int b = 0; b < 64; ++b) s += g_lpart[(size_t)b * NN + r];
    g_l[r] = s;
}

// ---------------------------------------------------------------------------
// Pass 2: O = (Ph*Vh + Ph*Vl + Pl*Vh) / l, fused 3-term, CTA 256x128 (m x d).
// K = 8192 in 256 chunks of 32.
// ---------------------------------------------------------------------------
__global__ __launch_bounds__(512, 1)
void pass2_kernel(float* __restrict__ outp) {
    extern __shared__ __align__(128) char smem[];
    const int t = threadIdx.x, wid = t >> 5, lane = t & 31;
    const int n0 = blockIdx.x * 128, m0 = blockIdx.y * 256;
    const uint32_t sb = smem_u32(smem);
    const int wr = wid >> 2, wc = wid & 3;

    FUSED_PRO();
    FUSED_LOOP(gP_hi, gP_lo, gvt_hi, gvt_lo, 256, NN);

    // epilogue: divide by l, store
#pragma unroll
    for (int mi = 0; mi < 4; ++mi) {
#pragma unroll
        for (int h = 0; h < 2; ++h) {
            int row = m0 + wr * 64 + mi * 16 + (lane >> 2) + h * 8;
            float inv = 1.0f / g_l[row];
#pragma unroll
            for (int ni = 0; ni < 4; ++ni) {
                int col = n0 + wc * 32 + ni * 8 + (lane & 3) * 2;
                float2 o;
                o.x = acc[mi][ni][h * 2] * inv;
                o.y = acc[mi][ni][h * 2 + 1] * inv;
                *(float2*)(outp + (size_t)row * DD + col) = o;
            }
        }
    }
}

// ---------------------------------------------------------------------------
extern "C" void kernel_launch(void* const* d_in, const int* in_sizes, int n_in,
                              void* d_out, int out_size) {
    const float* x       = (const float*)d_in[0];
    const float* spatial = (const float*)d_in[1];
    const float* edge    = (const float*)d_in[2];
    const float* Wq      = (const float*)d_in[3];
    const float* bq      = (const float*)d_in[4];
    const float* Wk      = (const float*)d_in[5];
    const float* bk      = (const float*)d_in[6];
    const float* Wv      = (const float*)d_in[7];
    const float* bv      = (const float*)d_in[8];
    float* out           = (float*)d_out;

    const int smem_main  = 3 * STAGE_BYTES;          // 184320
    const int smem_pass1 = 3 * STAGE_BYTES + 4096;   // 188416

    cudaFuncSetAttribute(proj_kernel, cudaFuncAttributeMaxDynamicSharedMemorySize, smem_main);
    cudaFuncSetAttribute(pass1_kernel, cudaFuncAttributeMaxDynamicSharedMemorySize, smem_pass1);
    cudaFuncSetAttribute(pass2_kernel, cudaFuncAttributeMaxDynamicSharedMemorySize, smem_main);

    split_kernel<<<4864, 256>>>(x, Wq, Wk, Wv);
    proj_kernel<<<dim3(4, 32, 3), 512, smem_main>>>(bq, bk, bv);
    vtrans_kernel<<<dim3(NN / 32, DD / 32), 256>>>();
    pass1_kernel<<<dim3(64, 32), 512, smem_pass1>>>(spatial, edge);
    lreduce_kernel<<<32, 256>>>();
    pass2_kernel<<<dim3(4, 32), 512, smem_main>>>(out);
}

// round 9
// speedup vs baseline: 1.0784x; 1.0784x over previous
#include <cuda_runtime.h>
#include <cuda_bf16.h>
#include <stdint.h>
#include <math.h>

#define NN 8192
#define DD 512
#define SCALE 0.044194173824159216f

// ----------------- device scratch (allocation-free rule) -----------------
__device__ float g_v[NN * DD];
__device__ __nv_bfloat16 gx_hi[NN * DD], gx_lo[NN * DD];
__device__ __nv_bfloat16 gw_hi[3 * DD * DD], gw_lo[3 * DD * DD];
__device__ __nv_bfloat16 gq_hi[NN * DD], gq_lo[NN * DD];
__device__ __nv_bfloat16 gk_hi[NN * DD], gk_lo[NN * DD];
__device__ __nv_bfloat16 gvt_hi[DD * NN], gvt_lo[DD * NN];
__device__ __nv_bfloat16 gP_hi[(size_t)NN * NN], gP_lo[(size_t)NN * NN];
__device__ float g_lpart[64 * NN];
__device__ float g_l[NN];

// ----------------- helpers -----------------
__device__ __forceinline__ uint32_t smem_u32(const void* p) {
    uint32_t a;
    asm("{ .reg .u64 t; cvta.to.shared.u64 t, %1; cvt.u32.u64 %0, t; }" : "=r"(a) : "l"(p));
    return a;
}
__device__ __forceinline__ uint32_t pack2(__nv_bfloat16 a, __nv_bfloat16 b) {
    return (uint32_t)__bfloat16_as_ushort(a) | ((uint32_t)__bfloat16_as_ushort(b) << 16);
}
__device__ __forceinline__ void cpa16(uint32_t dst, const void* src) {
    asm volatile("cp.async.cg.shared.global [%0], [%1], 16;" :: "r"(dst), "l"(src));
}
__device__ __forceinline__ void cpa_commit() {
    asm volatile("cp.async.commit_group;" ::: "memory");
}
__device__ __forceinline__ void ldsm4(uint32_t* r, uint32_t addr) {
    asm volatile("ldmatrix.sync.aligned.m8n8.x4.shared.b16 {%0,%1,%2,%3}, [%4];"
                 : "=r"(r[0]), "=r"(r[1]), "=r"(r[2]), "=r"(r[3]) : "r"(addr));
}
__device__ __forceinline__ void mma16816(float* c, const uint32_t* a, const uint32_t* b) {
    asm volatile(
        "mma.sync.aligned.m16n8k16.row.col.f32.bf16.bf16.f32 "
        "{%0,%1,%2,%3}, {%4,%5,%6,%7}, {%8,%9}, {%0,%1,%2,%3};"
        : "+f"(c[0]), "+f"(c[1]), "+f"(c[2]), "+f"(c[3])
        : "r"(a[0]), "r"(a[1]), "r"(a[2]), "r"(a[3]), "r"(b[0]), "r"(b[1]));
}

// ---------------------------------------------------------------------------
// Split x and Wq/Wk/Wv into bf16 hi/lo
// ---------------------------------------------------------------------------
__global__ __launch_bounds__(256)
void split_kernel(const float* __restrict__ x, const float* __restrict__ Wq,
                  const float* __restrict__ Wk, const float* __restrict__ Wv) {
    int i4 = blockIdx.x * 256 + threadIdx.x;
    const float4* src;
    uint2 *oh, *ol;
    int off;
    if (i4 < NN * DD / 4) {
        src = (const float4*)x; oh = (uint2*)gx_hi; ol = (uint2*)gx_lo; off = i4;
    } else {
        int r = i4 - NN * DD / 4;
        int wi = r >> 16, rr = r & 65535;
        const float* w = (wi == 0) ? Wq : (wi == 1) ? Wk : Wv;
        src = (const float4*)w; off = rr;
        oh = (uint2*)(gw_hi + (size_t)wi * DD * DD);
        ol = (uint2*)(gw_lo + (size_t)wi * DD * DD);
    }
    float4 v = src[off];
    __nv_bfloat16 h0 = __float2bfloat16(v.x), h1 = __float2bfloat16(v.y);
    __nv_bfloat16 h2 = __float2bfloat16(v.z), h3 = __float2bfloat16(v.w);
    uint2 H, L;
    H.x = pack2(h0, h1);
    H.y = pack2(h2, h3);
    L.x = pack2(__float2bfloat16(v.x - __bfloat162float(h0)),
                __float2bfloat16(v.y - __bfloat162float(h1)));
    L.y = pack2(__float2bfloat16(v.z - __bfloat162float(h2)),
                __float2bfloat16(v.w - __bfloat162float(h3)));
    oh[off] = H;
    ol[off] = L;
}

// ---------------------------------------------------------------------------
// Fused-term GEMM body (CTA 128x128, warps 2x4, warp 64x32).
// Stage layout per buffer (40960B): Ah@0, Al@10240, Bh@20480, Bl@30720.
// COMPUTE: B-frags hoisted (shared by all mi), per-mi A loads -> compiler can
// overlap mi+1 A-ldsm under mi's MMAs (live regs ~104 < 128).
// ---------------------------------------------------------------------------
#define FUSED_STAGE(AH, AL, BH, BL, cc, buf, LDA)                                 \
    {                                                                             \
        int kk_ = (cc) * 32;                                                      \
        uint32_t d_ = sb + (buf) * 40960;                                         \
        const __nv_bfloat16* ah_ = (AH) + (size_t)m0 * (LDA) + kk_;               \
        const __nv_bfloat16* al_ = (AL) + (size_t)m0 * (LDA) + kk_;               \
        const __nv_bfloat16* bh_ = (BH) + (size_t)n0 * (LDA) + kk_;               \
        const __nv_bfloat16* bl_ = (BL) + (size_t)n0 * (LDA) + kk_;               \
        _Pragma("unroll")                                                         \
        for (int i_ = 0; i_ < 2; ++i_) {                                          \
            int r_ = sr + i_ * 64;                                                \
            uint32_t ro_ = r_ * 80 + sc * 16;                                     \
            size_t go_ = (size_t)r_ * (LDA) + sc * 8;                             \
            cpa16(d_ + ro_, ah_ + go_);                                           \
            cpa16(d_ + 10240 + ro_, al_ + go_);                                   \
            cpa16(d_ + 20480 + ro_, bh_ + go_);                                   \
            cpa16(d_ + 30720 + ro_, bl_ + go_);                                   \
        }                                                                         \
        cpa_commit();                                                             \
    }

#define FUSED_COMPUTE(cc)                                                         \
    {                                                                             \
        uint32_t sA = sb + ((cc) & 1) * 40960, sB = sA + 20480;                   \
        _Pragma("unroll")                                                         \
        for (int kq = 0; kq < 2; ++kq) {                                          \
            uint32_t bh[2][4], bl[2][4];                                          \
            _Pragma("unroll")                                                     \
            for (int nj = 0; nj < 2; ++nj) {                                      \
                ldsm4(bh[nj], sB + bOff + nj * 1280 + kq * 32);                   \
                ldsm4(bl[nj], sB + 10240 + bOff + nj * 1280 + kq * 32);           \
            }                                                                     \
            _Pragma("unroll")                                                     \
            for (int mi = 0; mi < 4; ++mi) {                                      \
                uint32_t ah[4], al[4];                                            \
                ldsm4(ah, sA + aOff + mi * 1280 + kq * 32);                       \
                ldsm4(al, sA + 10240 + aOff + mi * 1280 + kq * 32);               \
                _Pragma("unroll")                                                 \
                for (int nj = 0; nj < 2; ++nj) {                                  \
                    mma16816(acc[mi][nj * 2], ah, bh[nj]);                        \
                    mma16816(acc[mi][nj * 2 + 1], ah, bh[nj] + 2);                \
                    mma16816(acc[mi][nj * 2], ah, bl[nj]);                        \
                    mma16816(acc[mi][nj * 2 + 1], ah, bl[nj] + 2);                \
                    mma16816(acc[mi][nj * 2], al, bh[nj]);                        \
                    mma16816(acc[mi][nj * 2 + 1], al, bh[nj] + 2);                \
                }                                                                 \
            }                                                                     \
        }                                                                         \
    }

// ---------------------------------------------------------------------------
// Tensor-core QKV projection, fused 3-term. z=0:Q, z=1:K (bf16 hi/lo), z=2:V fp32.
// ---------------------------------------------------------------------------
__global__ __launch_bounds__(256, 2)
void proj_kernel(const float* __restrict__ bq, const float* __restrict__ bk,
                 const float* __restrict__ bv) {
    extern __shared__ __align__(128) char smem[];
    const int t = threadIdx.x, wid = t >> 5, lane = t & 31;
    const int z = blockIdx.z;
    const int m0 = blockIdx.y * 128, n0 = blockIdx.x * 128;
    const uint32_t sb = smem_u32(smem);
    const int wr = wid >> 2, wc = wid & 3;
    const __nv_bfloat16* WHz = gw_hi + (size_t)z * DD * DD;
    const __nv_bfloat16* WLz = gw_lo + (size_t)z * DD * DD;

    float acc[4][4][4];
#pragma unroll
    for (int mi = 0; mi < 4; ++mi)
#pragma unroll
        for (int ni = 0; ni < 4; ++ni)
#pragma unroll
            for (int q = 0; q < 4; ++q) acc[mi][ni][q] = 0.0f;

    const int sr = t >> 2, sc = t & 3;
    const uint32_t aOff = (uint32_t)(wr * 64 + (lane & 15)) * 80 + (lane >> 4) * 16;
    const uint32_t bOff = (uint32_t)(wc * 32 + (lane & 7) + ((lane >> 4) & 1) * 8) * 80 +
                          ((lane >> 3) & 1) * 16;

    FUSED_STAGE(gx_hi, gx_lo, WHz, WLz, 0, 0, DD);
    for (int cc = 0; cc < 16; ++cc) {
        asm volatile("cp.async.wait_group 0;" ::: "memory");
        __syncthreads();
        if (cc < 15) FUSED_STAGE(gx_hi, gx_lo, WHz, WLz, cc + 1, (cc + 1) & 1, DD);
        FUSED_COMPUTE(cc);
    }

    const float* bias = (z == 0) ? bq : (z == 1) ? bk : bv;
#pragma unroll
    for (int mi = 0; mi < 4; ++mi) {
#pragma unroll
        for (int h = 0; h < 2; ++h) {
            int row = m0 + wr * 64 + mi * 16 + (lane >> 2) + h * 8;
#pragma unroll
            for (int ni = 0; ni < 4; ++ni) {
                int col = n0 + wc * 32 + ni * 8 + (lane & 3) * 2;
                float2 bb = *(const float2*)(bias + col);
                float v0 = acc[mi][ni][h * 2] + bb.x;
                float v1 = acc[mi][ni][h * 2 + 1] + bb.y;
                if (z == 2) {
                    *(float2*)(g_v + (size_t)row * DD + col) = make_float2(v0, v1);
                } else {
                    __nv_bfloat16* oh = z ? gk_hi : gq_hi;
                    __nv_bfloat16* ol = z ? gk_lo : gq_lo;
                    __nv_bfloat16 h0 = __float2bfloat16(v0), h1 = __float2bfloat16(v1);
                    *(uint32_t*)(oh + (size_t)row * DD + col) = pack2(h0, h1);
                    *(uint32_t*)(ol + (size_t)row * DD + col) =
                        pack2(__float2bfloat16(v0 - __bfloat162float(h0)),
                              __float2bfloat16(v1 - __bfloat162float(h1)));
                }
            }
        }
    }
}

// ---------------------------------------------------------------------------
// V transpose + bf16 split
// ---------------------------------------------------------------------------
__global__ __launch_bounds__(256, 4)
void vtrans_kernel() {
    __shared__ float ts[32][33];
    int j0 = blockIdx.x * 32, d0 = blockIdx.y * 32;
    int tx = threadIdx.x & 31, ty = threadIdx.x >> 5;
#pragma unroll
    for (int i = 0; i < 4; ++i)
        ts[ty + 8 * i][tx] = g_v[(size_t)(j0 + ty + 8 * i) * DD + d0 + tx];
    __syncthreads();
#pragma unroll
    for (int i = 0; i < 4; ++i) {
        float v = ts[tx][ty + 8 * i];
        __nv_bfloat16 h = __float2bfloat16(v);
        __nv_bfloat16 l = __float2bfloat16(v - __bfloat162float(h));
        size_t o = (size_t)(d0 + ty + 8 * i) * NN + j0 + tx;
        gvt_hi[o] = h;
        gvt_lo[o] = l;
    }
}

// ---------------------------------------------------------------------------
// Pass 1: P = exp(scale*Q@K^T + sp + ed), fused 3-term mainloop.
// ---------------------------------------------------------------------------
__global__ __launch_bounds__(256, 2)
void pass1_kernel(const float* __restrict__ sp, const float* __restrict__ ed) {
    extern __shared__ __align__(128) char smem[];
    float* smem_l = (float*)(smem + 81920);
    const int t = threadIdx.x, wid = t >> 5, lane = t & 31;
    const int m0 = blockIdx.y * 128, n0 = blockIdx.x * 128;
    const uint32_t sb = smem_u32(smem);
    const int wr = wid >> 2, wc = wid & 3;

    float acc[4][4][4];
#pragma unroll
    for (int mi = 0; mi < 4; ++mi)
#pragma unroll
        for (int ni = 0; ni < 4; ++ni)
#pragma unroll
            for (int q = 0; q < 4; ++q) acc[mi][ni][q] = 0.0f;

    const int sr = t >> 2, sc = t & 3;
    const uint32_t aOff = (uint32_t)(wr * 64 + (lane & 15)) * 80 + (lane >> 4) * 16;
    const uint32_t bOff = (uint32_t)(wc * 32 + (lane & 7) + ((lane >> 4) & 1) * 8) * 80 +
                          ((lane >> 3) & 1) * 16;

    FUSED_STAGE(gq_hi, gq_lo, gk_hi, gk_lo, 0, 0, DD);
    for (int cc = 0; cc < 16; ++cc) {
        asm volatile("cp.async.wait_group 0;" ::: "memory");
        __syncthreads();
        if (cc < 15) FUSED_STAGE(gq_hi, gq_lo, gk_hi, gk_lo, cc + 1, (cc + 1) & 1, DD);
        FUSED_COMPUTE(cc);
    }

    // epilogue: bias add, exp, split-store P, row sums
#pragma unroll
    for (int mi = 0; mi < 4; ++mi) {
#pragma unroll
        for (int h = 0; h < 2; ++h) {
            int rloc = wr * 64 + mi * 16 + (lane >> 2) + h * 8;
            size_t rb = (size_t)(m0 + rloc) * NN;
            float rs = 0.0f;
#pragma unroll
            for (int ni = 0; ni < 4; ++ni) {
                int col = n0 + wc * 32 + ni * 8 + (lane & 3) * 2;
                float2 s2 = *(const float2*)(sp + rb + col);
                float2 e2 = *(const float2*)(ed + rb + col);
                float p0 = __expf(acc[mi][ni][h * 2] * SCALE + s2.x + e2.x);
                float p1 = __expf(acc[mi][ni][h * 2 + 1] * SCALE + s2.y + e2.y);
                __nv_bfloat16 h0 = __float2bfloat16(p0), h1 = __float2bfloat16(p1);
                *(uint32_t*)(gP_hi + rb + col) = pack2(h0, h1);
                *(uint32_t*)(gP_lo + rb + col) =
                    pack2(__float2bfloat16(p0 - __bfloat162float(h0)),
                          __float2bfloat16(p1 - __bfloat162float(h1)));
                rs += p0 + p1;
            }
            rs += __shfl_xor_sync(0xffffffffu, rs, 1);
            rs += __shfl_xor_sync(0xffffffffu, rs, 2);
            if ((lane & 3) == 0) smem_l[rloc * 4 + wc] = rs;
        }
    }
    __syncthreads();
    if (t < 128) {
        float s = smem_l[t * 4] + smem_l[t * 4 + 1] + smem_l[t * 4 + 2] + smem_l[t * 4 + 3];
        g_lpart[(size_t)blockIdx.x * NN + m0 + t] = s;
    }
}

// ---------------------------------------------------------------------------
// l reduce (deterministic)
// ---------------------------------------------------------------------------
__global__ void lreduce_kernel() {
    int r = blockIdx.x * 256 + threadIdx.x;
    float s = 0.0f;
    for (int b = 0; b < 64; ++b) s += g_lpart[(size_t)b * NN + r];
    g_l[r] = s;
}

// ---------------------------------------------------------------------------
// Pass 2: O = (Ph*Vh + Ph*Vl + Pl*Vh) / l, fused 3-term, pass1 topology.
// CTA 128x128 (m x d), warps 2x4 (warp 64x32). A=gP (stride NN), B=gvt (stride NN).
// K = 8192 in 256 chunks of 32.
// ---------------------------------------------------------------------------
__global__ __launch_bounds__(256, 2)
void pass2_kernel(float* __restrict__ outp) {
    extern __shared__ __align__(128) char smem[];
    const int t = threadIdx.x, wid = t >> 5, lane = t & 31;
    const int n0 = blockIdx.x * 128, m0 = blockIdx.y * 128;
    const uint32_t sb = smem_u32(smem);
    const int wr = wid >> 2, wc = wid & 3;

    float acc[4][4][4];
#pragma unroll
    for (int mi = 0; mi < 4; ++mi)
#pragma unroll
        for (int ni = 0; ni < 4; ++ni)
#pragma unroll
            for (int q = 0; q < 4; ++q) acc[mi][ni][q] = 0.0f;

    const int sr = t >> 2, sc = t & 3;
    const uint32_t aOff = (uint32_t)(wr * 64 + (lane & 15)) * 80 + (lane >> 4) * 16;
    const uint32_t bOff = (uint32_t)(wc * 32 + (lane & 7) + ((lane >> 4) & 1) * 8) * 80 +
                          ((lane >> 3) & 1) * 16;

    FUSED_STAGE(gP_hi, gP_lo, gvt_hi, gvt_lo, 0, 0, NN);
    for (int cc = 0; cc < 256; ++cc) {
        asm volatile("cp.async.wait_group 0;" ::: "memory");
        __syncthreads();
        if (cc < 255) FUSED_STAGE(gP_hi, gP_lo, gvt_hi, gvt_lo, cc + 1, (cc + 1) & 1, NN);
        FUSED_COMPUTE(cc);
    }

    // epilogue: divide by l, store
#pragma unroll
    for (int mi = 0; mi < 4; ++mi) {
#pragma unroll
        for (int h = 0; h < 2; ++h) {
            int row = m0 + wr * 64 + mi * 16 + (lane >> 2) + h * 8;
            float inv = 1.0f / g_l[row];
#pragma unroll
            for (int ni = 0; ni < 4; ++ni) {
                int col = n0 + wc * 32 + ni * 8 + (lane & 3) * 2;
                float2 o;
                o.x = acc[mi][ni][h * 2] * inv;
                o.y = acc[mi][ni][h * 2 + 1] * inv;
                *(float2*)(outp + (size_t)row * DD + col) = o;
            }
        }
    }
}

// ---------------------------------------------------------------------------
extern "C" void kernel_launch(void* const* d_in, const int* in_sizes, int n_in,
                              void* d_out, int out_size) {
    const float* x       = (const float*)d_in[0];
    const float* spatial = (const float*)d_in[1];
    const float* edge    = (const float*)d_in[2];
    const float* Wq      = (const float*)d_in[3];
    const float* bq      = (const float*)d_in[4];
    const float* Wk      = (const float*)d_in[5];
    const float* bk      = (const float*)d_in[6];
    const float* Wv      = (const float*)d_in[7];
    const float* bv      = (const float*)d_in[8];
    float* out           = (float*)d_out;

    cudaFuncSetAttribute(proj_kernel, cudaFuncAttributeMaxDynamicSharedMemorySize, 81920);
    cudaFuncSetAttribute(pass1_kernel, cudaFuncAttributeMaxDynamicSharedMemorySize, 84480);
    cudaFuncSetAttribute(pass2_kernel, cudaFuncAttributeMaxDynamicSharedMemorySize, 81920);

    split_kernel<<<4864, 256>>>(x, Wq, Wk, Wv);
    proj_kernel<<<dim3(4, 64, 3), 256, 81920>>>(bq, bk, bv);
    vtrans_kernel<<<dim3(NN / 32, DD / 32), 256>>>();
    pass1_kernel<<<dim3(64, 64), 256, 84480>>>(spatial, edge);
    lreduce_kernel<<<32, 256>>>();
    pass2_kernel<<<dim3(4, 64), 256, 81920>>>(out);
}